// round 6
// baseline (speedup 1.0000x reference)
#include <cuda_runtime.h>
#include <cstdint>

#define MQ     50000
#define NSUP   100000
#define HN     32
#define KPN    15
#define CIN    64
#define COUT   64
#define GK     (KPN * CIN)        // 960
#define MB     16
#define INFPT  1.0e6f

#define NSTEP  (GK / 8)           // 120 k8 steps
#define TILE_M 128

__device__ int g_idx_is64;
__device__ unsigned char g_flags[NSUP];
__device__ float g_inv[MQ];
__device__ float g_wgt[(size_t)MQ * GK];        // [m][k*64+c], tf32-rounded
__device__ float g_Bp[NSTEP * 8 * 32 * 4];      // fragment-packed W, hi/lo split

__device__ __forceinline__ float to_tf32(float x) {
    uint32_t r; asm("cvt.rna.tf32.f32 %0, %1;" : "=r"(r) : "f"(x));
    return __uint_as_float(r);
}
__device__ __forceinline__ void mma_tf32(float4& c, uint32_t a0, uint32_t a1,
                                         uint32_t a2, uint32_t a3,
                                         uint32_t b0, uint32_t b1) {
    asm volatile(
        "mma.sync.aligned.m16n8k8.row.col.f32.tf32.tf32.f32 "
        "{%0,%1,%2,%3}, {%4,%5,%6,%7}, {%8,%9}, {%0,%1,%2,%3};"
        : "+f"(c.x), "+f"(c.y), "+f"(c.z), "+f"(c.w)
        : "r"(a0), "r"(a1), "r"(a2), "r"(a3), "r"(b0), "r"(b1));
}

// ================= prep: flags + B fragment pack + dtype detect ==============
#define FLAG_BLKS ((NSUP + 7) / 8)
#define BP_BLKS   (NSTEP * 8 * 32 / 256)     // 120
__global__ void __launch_bounds__(256) prep_kernel(const float* __restrict__ sfeats,
                                                   const float* __restrict__ wts,
                                                   const unsigned* __restrict__ nbr) {
    const int b = blockIdx.x;
    const int tid = threadIdx.x;

    if (b < FLAG_BLKS) {
        const int n = b * 8 + (tid >> 5);
        if (n >= NSUP) return;
        const int lane = tid & 31;
        const float* row = sfeats + (long long)n * CIN;
        float s = row[lane] + row[lane + 32];
        #pragma unroll
        for (int o = 16; o; o >>= 1) s += __shfl_xor_sync(0xffffffffu, s, o);
        if (lane == 0) g_flags[n] = (s > 0.0f) ? 1 : 0;
        return;
    }
    if (b < FLAG_BLKS + BP_BLKS) {
        const int e = (b - FLAG_BLKS) * 256 + tid;   // float4 index, < 30720
        const int lane = e & 31;
        const int t    = (e >> 5) & 7;
        const int step = e >> 8;
        const int kc0 = step * 8 + (lane & 3);
        const int d   = t * 8 + (lane >> 2);
        const float w0 = wts[kc0 * COUT + d];
        const float w1 = wts[(kc0 + 4) * COUT + d];
        const float h0 = to_tf32(w0), h1 = to_tf32(w1);
        const float l0 = to_tf32(w0 - h0), l1 = to_tf32(w1 - h1);
        ((float4*)g_Bp)[e] = make_float4(h0, h1, l0, l1);
        return;
    }
    if (tid == 0) {
        int is64 = 1;
        #pragma unroll
        for (int i = 0; i < 64; i++) {
            if (nbr[2 * i + 1] != 0u) { is64 = 0; break; }
        }
        g_idx_is64 = is64;
    }
}

// ================= K1: stages A+B -> g_wgt, g_inv =================
__global__ void __launch_bounds__(512, 2)
k1_kernel(const float* __restrict__ qpts,
          const float* __restrict__ spts,
          const float* __restrict__ sfeats,
          const void*  __restrict__ nbr,
          const float* __restrict__ kpts)
{
    __shared__ float w_s[MB * HN * 16];
    __shared__ int   idx_s[MB * HN];
    __shared__ float kp_s[48];

    const int tid = threadIdx.x;
    const int m0  = blockIdx.x * MB;
    const bool is64 = (g_idx_is64 != 0);

    if (tid < KPN * 3) kp_s[tid] = kpts[tid];
    __syncthreads();

    // ---- Stage A: warp per query (m = tid>>5), h = lane ----
    {
        const int m = tid >> 5;
        const int h = tid & 31;
        const long long gi = (long long)(m0 + m) * HN + h;
        int idx;
        if (is64) idx = (int)((const long long*)nbr)[gi];
        else      idx = ((const int*)nbr)[gi];
        const bool valid = (idx < NSUP);

        float px, py, pz;
        if (valid) {
            const float* s3 = spts + (long long)idx * 3;
            px = s3[0]; py = s3[1]; pz = s3[2];
        } else {
            px = INFPT; py = INFPT; pz = INFPT;
        }
        const float* q3 = qpts + (long long)(m0 + m) * 3;
        const float rx = px - q3[0];
        const float ry = py - q3[1];
        const float rz = pz - q3[2];

        float* wrow = w_s + tid * 16;
        float wmax = 0.0f;
        #pragma unroll
        for (int k = 0; k < KPN; k++) {
            const float dx = rx - kp_s[k * 3 + 0];
            const float dy = ry - kp_s[k * 3 + 1];
            const float dz = rz - kp_s[k * 3 + 2];
            const float sq = dx * dx + dy * dy + dz * dz;
            const float w  = fmaxf(1.0f - sqrtf(sq) * 0.5f, 0.0f);
            wrow[k] = w;
            wmax = fmaxf(wmax, w);
        }

        bool real = false;
        if (valid) real = (g_flags[idx] != 0);
        const unsigned bal = __ballot_sync(0xffffffffu, real);
        if (h == 0) g_inv[m0 + m] = 1.0f / (float)max(__popc(bal), 1);

        idx_s[tid] = (wmax > 0.0f) ? idx : -1;
    }
    __syncthreads();

    // ---- Stage B: warp per query, thread owns channel pair (2*lane, 2*lane+1)
    {
        const int m    = tid >> 5;
        const int lane = tid & 31;
        const int c0   = 2 * lane;

        float acc[KPN][2];
        #pragma unroll
        for (int k = 0; k < KPN; k++) { acc[k][0] = 0.0f; acc[k][1] = 0.0f; }

        const int*   irow  = idx_s + m * HN;
        const float* wbase = w_s + m * HN * 16;

        #pragma unroll 4
        for (int h = 0; h < HN; h++) {
            const int idx = irow[h];          // warp-uniform branch
            if (idx >= 0) {
                const float2 f = *(const float2*)(sfeats + (long long)idx * CIN + c0);
                const float* wr = wbase + h * 16;
                float wk[16];
                *(float4*)&wk[0]  = *(const float4*)(wr + 0);
                *(float4*)&wk[4]  = *(const float4*)(wr + 4);
                *(float4*)&wk[8]  = *(const float4*)(wr + 8);
                *(float4*)&wk[12] = *(const float4*)(wr + 12);
                #pragma unroll
                for (int k = 0; k < KPN; k++) {
                    acc[k][0] = fmaf(wk[k], f.x, acc[k][0]);
                    acc[k][1] = fmaf(wk[k], f.y, acc[k][1]);
                }
            }
        }

        float* orow = g_wgt + (size_t)(m0 + m) * GK + c0;
        #pragma unroll
        for (int k = 0; k < KPN; k++) {
            *(float2*)(orow + k * CIN) =
                make_float2(to_tf32(acc[k][0]), to_tf32(acc[k][1]));
        }
    }
}

// ================= K2: mma.sync tf32 GEMM: out = g_wgt @ W, scaled ===========
__global__ void __launch_bounds__(256)
gemm_kernel(float* __restrict__ out)
{
    __shared__ float As[TILE_M * 68];        // k-chunk of A, pad 68 (conflict-free)

    const int tid  = threadIdx.x;
    const int wid  = tid >> 5;
    const int lane = tid & 31;
    const int m0   = blockIdx.x * TILE_M;
    const int q    = lane & 3;
    const int g4   = lane >> 2;
    const int mloc = wid * 16 + g4;

    float4 acc[8];
    #pragma unroll
    for (int t = 0; t < 8; t++) acc[t] = make_float4(0.f, 0.f, 0.f, 0.f);

    #pragma unroll 1
    for (int ch = 0; ch < 15; ch++) {
        // stage A chunk: rows m0..m0+127, cols ch*64..ch*64+63
        #pragma unroll
        for (int t = 0; t < 8; t++) {
            const int i = t * 256 + tid;      // 0..2047
            const int r = i >> 4;
            const int c4 = (i & 15) * 4;
            int m = m0 + r;
            if (m >= MQ) m = MQ - 1;
            const float4 v = *(const float4*)(g_wgt + (size_t)m * GK + ch * 64 + c4);
            *(float4*)(As + r * 68 + c4) = v;
        }
        __syncthreads();

        #pragma unroll
        for (int s = 0; s < 8; s++) {
            const int k0 = s * 8;
            const uint32_t a0 = __float_as_uint(As[mloc * 68 + k0 + q]);
            const uint32_t a1 = __float_as_uint(As[(mloc + 8) * 68 + k0 + q]);
            const uint32_t a2 = __float_as_uint(As[mloc * 68 + k0 + q + 4]);
            const uint32_t a3 = __float_as_uint(As[(mloc + 8) * 68 + k0 + q + 4]);
            const float4* bp = (const float4*)g_Bp + ((ch * 8 + s) * 8) * 32 + lane;
            #pragma unroll
            for (int t = 0; t < 8; t++) {
                const float4 b = bp[t * 32];
                mma_tf32(acc[t], a0, a1, a2, a3,
                         __float_as_uint(b.x), __float_as_uint(b.y));   // hi
                mma_tf32(acc[t], a0, a1, a2, a3,
                         __float_as_uint(b.z), __float_as_uint(b.w));   // lo
            }
        }
        __syncthreads();
    }

    // epilogue: scale by 1/nbr_num and store
    const int mrow0 = m0 + wid * 16 + g4;
    const int mrow1 = mrow0 + 8;
    const float inv0 = (mrow0 < MQ) ? g_inv[mrow0] : 0.0f;
    const float inv1 = (mrow1 < MQ) ? g_inv[mrow1] : 0.0f;
    #pragma unroll
    for (int t = 0; t < 8; t++) {
        const int col = t * 8 + 2 * q;
        if (mrow0 < MQ)
            *(float2*)(out + (size_t)mrow0 * COUT + col) =
                make_float2(acc[t].x * inv0, acc[t].y * inv0);
        if (mrow1 < MQ)
            *(float2*)(out + (size_t)mrow1 * COUT + col) =
                make_float2(acc[t].z * inv1, acc[t].w * inv1);
    }
}

// ================= launch =================
extern "C" void kernel_launch(void* const* d_in, const int* in_sizes, int n_in,
                              void* d_out, int out_size) {
    const float* qpts = nullptr;
    const float* spts = nullptr;
    const float* sfeats = nullptr;
    const void*  nbr = nullptr;
    const float* wts = nullptr;
    const float* kpts = nullptr;
    for (int i = 0; i < n_in; i++) {
        switch (in_sizes[i]) {
            case MQ * 3:        qpts   = (const float*)d_in[i]; break;
            case NSUP * 3:      spts   = (const float*)d_in[i]; break;
            case NSUP * CIN:    sfeats = (const float*)d_in[i]; break;
            case MQ * HN:       nbr    = d_in[i];               break;
            case KPN*CIN*COUT:  wts    = (const float*)d_in[i]; break;
            case KPN * 3:       kpts   = (const float*)d_in[i]; break;
            default: break;
        }
    }
    float* outp = (float*)d_out;

    prep_kernel<<<FLAG_BLKS + BP_BLKS + 1, 256>>>(sfeats, wts, (const unsigned*)nbr);
    k1_kernel<<<MQ / MB, 512>>>(qpts, spts, sfeats, nbr, kpts);
    gemm_kernel<<<(MQ + TILE_M - 1) / TILE_M, 256>>>(outp);
}

// round 7
// speedup vs baseline: 2.0137x; 2.0137x over previous
#include <cuda_runtime.h>
#include <cstdint>

#define MQ     50000
#define NSUP   100000
#define HN     32
#define KPN    15
#define CIN    64
#define COUT   64
#define GK     (KPN * CIN)        // 960
#define MB     16
#define NTHR   256
#define INFPT  1.0e6f

#define NSTEP  (GK / 8)           // 120
#define APAD   972                // wgt_s row stride (972%32=12 -> conflict-free frags)

// smem words: w_s 8192 + wgt_s 16*972 + kp 48 + inv 16 + idx 512
#define SMEM_WORDS (MB*HN*16 + MB*APAD + 48 + MB + MB*HN)
#define SMEM_BYTES (SMEM_WORDS * 4)

__device__ int g_idx_is64;
__device__ unsigned char g_flags[NSUP];
// fragment-packed W (tf32): g_Bf[step][wn(8)][lane(32)] = float2{B[k0+q][d], B[k0+q+4][d]}
//   with q=lane&3, g4=lane>>2, d=wn*8+g4, B[kg][d] = wts[kg*COUT+d]
__device__ float2 g_Bf[NSTEP * 8 * 32];

__device__ __forceinline__ float to_tf32(float x) {
    uint32_t r; asm("cvt.rna.tf32.f32 %0, %1;" : "=r"(r) : "f"(x));
    return __uint_as_float(r);
}
__device__ __forceinline__ void mma_tf32(float4& c, uint32_t a0, uint32_t a1,
                                         uint32_t a2, uint32_t a3,
                                         uint32_t b0, uint32_t b1) {
    asm volatile(
        "mma.sync.aligned.m16n8k8.row.col.f32.tf32.tf32.f32 "
        "{%0,%1,%2,%3}, {%4,%5,%6,%7}, {%8,%9}, {%0,%1,%2,%3};"
        : "+f"(c.x), "+f"(c.y), "+f"(c.z), "+f"(c.w)
        : "r"(a0), "r"(a1), "r"(a2), "r"(a3), "r"(b0), "r"(b1));
}

// ================= prep: flags + B fragment pack + dtype detect ==============
#define FLAG_BLKS ((NSUP + 7) / 8)
#define BF_BLKS   (NSTEP * 8 * 32 / 256)     // 120
__global__ void __launch_bounds__(256) prep_kernel(const float* __restrict__ sfeats,
                                                   const float* __restrict__ wts,
                                                   const unsigned* __restrict__ nbr) {
    const int b = blockIdx.x;
    const int tid = threadIdx.x;

    if (b < FLAG_BLKS) {
        const int n = b * 8 + (tid >> 5);
        if (n >= NSUP) return;
        const int lane = tid & 31;
        const float* row = sfeats + (long long)n * CIN;
        float s = row[lane] + row[lane + 32];
        #pragma unroll
        for (int o = 16; o; o >>= 1) s += __shfl_xor_sync(0xffffffffu, s, o);
        if (lane == 0) g_flags[n] = (s > 0.0f) ? 1 : 0;
        return;
    }
    if (b < FLAG_BLKS + BF_BLKS) {
        const int e = (b - FLAG_BLKS) * 256 + tid;   // float2 index, < 30720
        const int lane = e & 31;
        const int wn   = (e >> 5) & 7;
        const int step = e >> 8;
        const int q  = lane & 3;
        const int g4 = lane >> 2;
        const int d  = wn * 8 + g4;
        const int kg0 = step * 8 + q;
        g_Bf[e] = make_float2(to_tf32(wts[kg0 * COUT + d]),
                              to_tf32(wts[(kg0 + 4) * COUT + d]));
        return;
    }
    if (tid == 0) {
        int is64 = 1;
        #pragma unroll
        for (int i = 0; i < 64; i++) {
            if (nbr[2 * i + 1] != 0u) { is64 = 0; break; }
        }
        g_idx_is64 = is64;
    }
}

// ================= fused main kernel =================
extern "C" __global__ void __launch_bounds__(NTHR, 2)
kpconv_kernel(const float* __restrict__ qpts,
              const float* __restrict__ spts,
              const float* __restrict__ sfeats,
              const void*  __restrict__ nbr,
              const float* __restrict__ kpts,
              float* __restrict__ out)
{
    extern __shared__ float sm[];
    float* w_s   = sm;                          // [MB][HN][16]
    float* wgt_s = sm + MB * HN * 16;           // [MB][APAD], tf32-rounded A
    float* kp_s  = wgt_s + MB * APAD;           // 48
    float* inv_s = kp_s + 48;                   // MB
    int*   idx_s = (int*)(inv_s + MB);          // [MB][HN]

    const int tid = threadIdx.x;
    const int m0  = blockIdx.x * MB;
    const bool is64 = (g_idx_is64 != 0);

    if (tid < KPN * 3) kp_s[tid] = kpts[tid];
    __syncthreads();

    // ---------------- Stage A: geometry weights w[m,h,k] -> smem ------------
    #pragma unroll
    for (int it = 0; it < 2; it++) {
        const int p = tid + it * NTHR;          // p < MB*HN = 512
        const int m = p >> 5;
        const int h = p & 31;
        const long long gi = (long long)(m0 + m) * HN + h;
        int idx;
        if (is64) idx = (int)((const long long*)nbr)[gi];
        else      idx = ((const int*)nbr)[gi];
        const bool valid = (idx < NSUP);

        float px, py, pz;
        if (valid) {
            const float* s3 = spts + (long long)idx * 3;
            px = s3[0]; py = s3[1]; pz = s3[2];
        } else {
            px = INFPT; py = INFPT; pz = INFPT;
        }
        const float* q3 = qpts + (long long)(m0 + m) * 3;
        const float rx = px - q3[0];
        const float ry = py - q3[1];
        const float rz = pz - q3[2];

        float* wrow = w_s + p * 16;
        float wmax = 0.0f;
        #pragma unroll
        for (int k = 0; k < KPN; k++) {
            const float dx = rx - kp_s[k * 3 + 0];
            const float dy = ry - kp_s[k * 3 + 1];
            const float dz = rz - kp_s[k * 3 + 2];
            const float sq = dx * dx + dy * dy + dz * dz;
            const float w  = fmaxf(1.0f - sqrtf(sq) * 0.5f, 0.0f);
            wrow[k] = w;
            wmax = fmaxf(wmax, w);
        }

        bool real = false;
        if (valid) real = (g_flags[idx] != 0);
        const unsigned bal = __ballot_sync(0xffffffffu, real);
        if ((tid & 31) == 0) inv_s[m] = 1.0f / (float)max(__popc(bal), 1);

        idx_s[p] = (wmax > 0.0f) ? idx : -1;
    }
    __syncthreads();

    // ---------------- Stage B: wgt_s[m][k*64+c] = sum_h w * f (tf32-rounded) -
    {
        const int g  = tid >> 4;
        const int j  = tid & 15;
        const int c0 = j * 4;

        float acc[KPN][4];
        #pragma unroll
        for (int k = 0; k < KPN; k++) {
            acc[k][0] = 0.0f; acc[k][1] = 0.0f; acc[k][2] = 0.0f; acc[k][3] = 0.0f;
        }
        const int*   irow  = idx_s + g * HN;
        const float* wbase = w_s + g * HN * 16;

        #pragma unroll 4
        for (int h = 0; h < HN; h++) {
            const int idx = irow[h];
            if (idx >= 0) {
                const float4 f = *(const float4*)(sfeats + (long long)idx * CIN + c0);
                const float* wr = wbase + h * 16;
                float wk[16];
                *(float4*)&wk[0]  = *(const float4*)(wr + 0);
                *(float4*)&wk[4]  = *(const float4*)(wr + 4);
                *(float4*)&wk[8]  = *(const float4*)(wr + 8);
                *(float4*)&wk[12] = *(const float4*)(wr + 12);
                #pragma unroll
                for (int k = 0; k < KPN; k++) {
                    acc[k][0] = fmaf(wk[k], f.x, acc[k][0]);
                    acc[k][1] = fmaf(wk[k], f.y, acc[k][1]);
                    acc[k][2] = fmaf(wk[k], f.z, acc[k][2]);
                    acc[k][3] = fmaf(wk[k], f.w, acc[k][3]);
                }
            }
        }

        float* wgrow = wgt_s + g * APAD + c0;
        #pragma unroll
        for (int k = 0; k < KPN; k++) {
            *(float4*)(wgrow + k * CIN) =
                make_float4(to_tf32(acc[k][0]), to_tf32(acc[k][1]),
                            to_tf32(acc[k][2]), to_tf32(acc[k][3]));
        }
    }
    __syncthreads();

    // ---------------- Stage C: out = wgt_s(16x960) @ W(960x64), mma.sync ----
    {
        const int wid  = tid >> 5;     // n8 tile: d in [8*wid, 8*wid+8)
        const int lane = tid & 31;
        const int q    = lane & 3;
        const int g4   = lane >> 2;

        float4 ca = make_float4(0.f, 0.f, 0.f, 0.f);
        float4 cb = make_float4(0.f, 0.f, 0.f, 0.f);

        const float* ar0 = wgt_s + g4 * APAD;
        const float* ar1 = wgt_s + (g4 + 8) * APAD;
        const float2* bp = g_Bf + wid * 32 + lane;

        #pragma unroll 4
        for (int s = 0; s < NSTEP; s += 2) {
            {
                const int k0 = s * 8;
                const uint32_t a0 = __float_as_uint(ar0[k0 + q]);
                const uint32_t a1 = __float_as_uint(ar1[k0 + q]);
                const uint32_t a2 = __float_as_uint(ar0[k0 + q + 4]);
                const uint32_t a3 = __float_as_uint(ar1[k0 + q + 4]);
                const float2 b = bp[(size_t)s * 256];
                mma_tf32(ca, a0, a1, a2, a3,
                         __float_as_uint(b.x), __float_as_uint(b.y));
            }
            {
                const int k0 = (s + 1) * 8;
                const uint32_t a0 = __float_as_uint(ar0[k0 + q]);
                const uint32_t a1 = __float_as_uint(ar1[k0 + q]);
                const uint32_t a2 = __float_as_uint(ar0[k0 + q + 4]);
                const uint32_t a3 = __float_as_uint(ar1[k0 + q + 4]);
                const float2 b = bp[(size_t)(s + 1) * 256];
                mma_tf32(cb, a0, a1, a2, a3,
                         __float_as_uint(b.x), __float_as_uint(b.y));
            }
        }
        ca.x += cb.x; ca.y += cb.y; ca.z += cb.z; ca.w += cb.w;

        // epilogue: rows g4, g4+8; cols wid*8 + 2q, +1
        const float inv0 = inv_s[g4];
        const float inv1 = inv_s[g4 + 8];
        const int col = wid * 8 + 2 * q;
        *(float2*)(out + (size_t)(m0 + g4) * COUT + col) =
            make_float2(ca.x * inv0, ca.y * inv0);
        *(float2*)(out + (size_t)(m0 + g4 + 8) * COUT + col) =
            make_float2(ca.z * inv1, ca.w * inv1);
    }
}

// ================= launch =================
extern "C" void kernel_launch(void* const* d_in, const int* in_sizes, int n_in,
                              void* d_out, int out_size) {
    const float* qpts = nullptr;
    const float* spts = nullptr;
    const float* sfeats = nullptr;
    const void*  nbr = nullptr;
    const float* wts = nullptr;
    const float* kpts = nullptr;
    for (int i = 0; i < n_in; i++) {
        switch (in_sizes[i]) {
            case MQ * 3:        qpts   = (const float*)d_in[i]; break;
            case NSUP * 3:      spts   = (const float*)d_in[i]; break;
            case NSUP * CIN:    sfeats = (const float*)d_in[i]; break;
            case MQ * HN:       nbr    = d_in[i];               break;
            case KPN*CIN*COUT:  wts    = (const float*)d_in[i]; break;
            case KPN * 3:       kpts   = (const float*)d_in[i]; break;
            default: break;
        }
    }
    float* outp = (float*)d_out;

    cudaFuncSetAttribute(kpconv_kernel,
                         cudaFuncAttributeMaxDynamicSharedMemorySize, SMEM_BYTES);

    prep_kernel<<<FLAG_BLKS + BF_BLKS + 1, 256>>>(sfeats, wts, (const unsigned*)nbr);
    kpconv_kernel<<<MQ / MB, NTHR, SMEM_BYTES>>>(
        qpts, spts, sfeats, nbr, kpts, outp);
}